// round 1
// baseline (speedup 1.0000x reference)
#include <cuda_runtime.h>
#include <math.h>

#define BSZ    16
#define KNEG   65536
#define KP1    65537            // K+1 logits per sample
#define NDIM   128
#define NDATA  1000000
#define INV_T  (1.0f / 0.07f)
#define EMA_M  0.5f

#define LOGITS (BSZ * KP1)      // 1,048,592
#define OUT_LZ_OFF   ((size_t)LOGITS)
#define OUT_MEM_OFF  ((size_t)2 * LOGITS)

__device__ double g_sum;

// ---------------------------------------------------------------------------
// Zero the global accumulator (must run every graph replay)
// ---------------------------------------------------------------------------
__global__ void k_init() { g_sum = 0.0; }

// ---------------------------------------------------------------------------
// One warp per (b, k): gather memory row, dot with x[b] and z[b], exp, store.
// Block-reduce the lx values into g_sum (double) with one atomic per block.
// ---------------------------------------------------------------------------
__global__ void __launch_bounds__(256) k_gather(
    const float* __restrict__ x, const float* __restrict__ z,
    const float* __restrict__ mem, const int* __restrict__ y,
    const int* __restrict__ idx, float* __restrict__ out)
{
    const int warp_in_blk = threadIdx.x >> 5;
    const int lane        = threadIdx.x & 31;
    const long long gwarp = (long long)blockIdx.x * (blockDim.x >> 5) + warp_in_blk;

    __shared__ double s_part[8];   // 256 threads = 8 warps

    float lx_val = 0.0f;

    if (gwarp < (long long)LOGITS) {
        const int b = (int)(gwarp / KP1);
        const int k = (int)(gwarp - (long long)b * KP1);

        // row index: broadcast load (all lanes read the same 4B address)
        int row;
        if (k == 0) row = __ldg(&y[b]);
        else        row = __ldg(&idx[(size_t)b * KNEG + (k - 1)]);

        // coalesced 512B row load: one float4 per lane
        const float4 w  = __ldg((const float4*)(mem + (size_t)row * NDIM) + lane);
        const float4 xv = __ldg((const float4*)(x   + (size_t)b   * NDIM) + lane);
        const float4 zv = __ldg((const float4*)(z   + (size_t)b   * NDIM) + lane);

        float dx = w.x * xv.x + w.y * xv.y + w.z * xv.z + w.w * xv.w;
        float dz = w.x * zv.x + w.y * zv.y + w.z * zv.z + w.w * zv.w;

        #pragma unroll
        for (int off = 16; off; off >>= 1) {
            dx += __shfl_xor_sync(0xffffffffu, dx, off);
            dz += __shfl_xor_sync(0xffffffffu, dz, off);
        }

        if (lane == 0) {
            lx_val       = expf(dx * INV_T);
            float lz_val = expf(dz * INV_T);
            out[(size_t)b * KP1 + k]              = lx_val;
            out[OUT_LZ_OFF + (size_t)b * KP1 + k] = lz_val;
        }
    }

    // block reduction of lx values (only lane 0 of each warp holds a value)
    if (lane == 0) s_part[warp_in_blk] = (double)lx_val;
    __syncthreads();
    if (threadIdx.x == 0) {
        double s = 0.0;
        #pragma unroll
        for (int i = 0; i < 8; i++) s += s_part[i];
        atomicAdd(&g_sum, s);
    }
}

// ---------------------------------------------------------------------------
// Scale lx and lz by 1/Z0 where Z0 = mean(lx) * NDATA
// ---------------------------------------------------------------------------
__global__ void __launch_bounds__(256) k_scale(float* __restrict__ out)
{
    const double z0  = g_sum / (double)LOGITS * (double)NDATA;
    const float  inv = (float)(1.0 / z0);

    const size_t n4 = (size_t)(2 * LOGITS) / 4;   // 524296 float4s (exact)
    size_t i = (size_t)blockIdx.x * blockDim.x + threadIdx.x;
    if (i < n4) {
        float4* p = (float4*)out;
        float4 v = p[i];
        v.x *= inv; v.y *= inv; v.z *= inv; v.w *= inv;
        p[i] = v;
    }
}

// ---------------------------------------------------------------------------
// EMA scatter update: row y[b] <- normalize(M*mem[y[b]] + (1-M)*x[b])
// One warp per sample. Runs after the bulk memcpy of memory -> out.
// ---------------------------------------------------------------------------
__global__ void __launch_bounds__(512) k_scatter(
    const float* __restrict__ x, const float* __restrict__ mem,
    const int* __restrict__ y, float* __restrict__ out_mem)
{
    const int b    = threadIdx.x >> 5;   // 16 warps
    const int lane = threadIdx.x & 31;
    if (b >= BSZ) return;

    const int row = __ldg(&y[b]);
    const float4 m  = __ldg((const float4*)(mem + (size_t)row * NDIM) + lane);
    const float4 xv = __ldg((const float4*)(x   + (size_t)b   * NDIM) + lane);

    float4 w;
    w.x = EMA_M * m.x + (1.0f - EMA_M) * xv.x;
    w.y = EMA_M * m.y + (1.0f - EMA_M) * xv.y;
    w.z = EMA_M * m.z + (1.0f - EMA_M) * xv.z;
    w.w = EMA_M * m.w + (1.0f - EMA_M) * xv.w;

    float nrm = w.x * w.x + w.y * w.y + w.z * w.z + w.w * w.w;
    #pragma unroll
    for (int off = 16; off; off >>= 1)
        nrm += __shfl_xor_sync(0xffffffffu, nrm, off);
    const float inv = rsqrtf(nrm);

    float4 o;
    o.x = w.x * inv; o.y = w.y * inv; o.z = w.z * inv; o.w = w.w * inv;
    ((float4*)(out_mem + (size_t)row * NDIM))[lane] = o;
}

// ---------------------------------------------------------------------------
extern "C" void kernel_launch(void* const* d_in, const int* in_sizes, int n_in,
                              void* d_out, int out_size)
{
    const float* x   = (const float*)d_in[0];
    const float* z   = (const float*)d_in[1];
    const float* mem = (const float*)d_in[2];
    const int*   y   = (const int*)  d_in[3];
    const int*   idx = (const int*)  d_in[4];
    float*       out = (float*)d_out;

    (void)in_sizes; (void)n_in; (void)out_size;

    // 1) reset accumulator
    k_init<<<1, 1>>>();

    // 2) gather + dual dot + exp + global sum.  One warp per logit.
    {
        const long long warps  = LOGITS;
        const int  wpb         = 256 / 32;
        const long long blocks = (warps + wpb - 1) / wpb;
        k_gather<<<(unsigned)blocks, 256>>>(x, z, mem, y, idx, out);
    }

    // 3) scale lx, lz by 1/Z0
    {
        const size_t n4     = (size_t)(2 * LOGITS) / 4;
        const size_t blocks = (n4 + 255) / 256;
        k_scale<<<(unsigned)blocks, 256>>>(out);
    }

    // 4) bulk copy memory -> new_memory region (full-BW memcpy path)
    cudaMemcpyAsync(out + OUT_MEM_OFF, mem,
                    (size_t)NDATA * NDIM * sizeof(float),
                    cudaMemcpyDeviceToDevice);

    // 5) EMA scatter update of the 16 touched rows
    k_scatter<<<1, 512>>>(x, mem, y, out + OUT_MEM_OFF);
}

// round 2
// speedup vs baseline: 1.4097x; 1.4097x over previous
#include <cuda_runtime.h>
#include <math.h>

#define BSZ    16
#define KNEG   65536
#define KP1    65537
#define NDIM   128
#define NDATA  1000000
#define INV_T  (1.0f / 0.07f)
#define EMA_M  0.5f

#define LOGITS       (BSZ * KP1)              // 1,048,592 = 4 * 262,148 exactly
#define TOT_WARPS    (LOGITS / 4)             // 262,148 gather warps, 4 rows each
#define GATHER_BLKS  ((TOT_WARPS + 7) / 8)    // 32,769 blocks of 8 warps
#define COPY_BLKS    (GATHER_BLKS / 3)        // 10,923
#define TOTAL_BLKS   (GATHER_BLKS + COPY_BLKS) // 43,692 (multiple of 4)

#define OUT_LZ_OFF   ((size_t)LOGITS)
#define OUT_MEM_OFF  ((size_t)2 * LOGITS)
#define N4_MEM       ((size_t)NDATA * NDIM / 4)     // 32,000,000 float4
#define N4_SCALE     ((size_t)2 * LOGITS / 4)       // 524,296 float4 (exact)

__device__ double g_sum;

__global__ void k_init() { g_sum = 0.0; }

// ---------------------------------------------------------------------------
// Fused: 3/4 of blocks gather+dot+exp, 1/4 stream-copy memory -> out.
// Gather layout: warp handles 4 rows, 8 lanes per row, 4 float4 per lane.
// ---------------------------------------------------------------------------
__global__ void __launch_bounds__(256) k_fused(
    const float* __restrict__ x, const float* __restrict__ z,
    const float* __restrict__ mem, const int* __restrict__ y,
    const int* __restrict__ idx, float* __restrict__ out)
{
    if ((blockIdx.x & 3) == 3) {
        // ---------------- streaming copy role ----------------
        const size_t cid    = (size_t)(blockIdx.x >> 2);
        const float4* src   = (const float4*)mem;
        float4*       dst   = (float4*)(out + OUT_MEM_OFF);
        const size_t stride = (size_t)COPY_BLKS * 256;
        for (size_t i = cid * 256 + threadIdx.x; i < N4_MEM; i += stride)
            __stcs(dst + i, __ldcs(src + i));
        return;
    }

    // ---------------- gather role ----------------
    const int gblk = (int)((blockIdx.x >> 2) * 3 + (blockIdx.x & 3));
    const int warp_in_blk = threadIdx.x >> 5;
    const int lane        = threadIdx.x & 31;
    const int grp         = lane >> 3;     // which of 4 rows
    const int li          = lane & 7;      // lane within row-group
    const long long warp_id = (long long)gblk * 8 + warp_in_blk;

    __shared__ double s_part[8];

    float lx_store = 0.0f;

    if (warp_id < (long long)TOT_WARPS) {
        const long long lg = warp_id * 4 + grp;      // logit index, always < LOGITS
        const int b = (int)(lg / KP1);
        const int k = (int)(lg - (long long)b * KP1);

        int row;
        if (k == 0) row = __ldg(&y[b]);
        else        row = __ldg(&idx[(size_t)b * KNEG + (k - 1)]);

        const float4* w4 = (const float4*)(mem + (size_t)row * NDIM);
        const float4* x4 = (const float4*)(x + b * NDIM);
        const float4* z4 = (const float4*)(z + b * NDIM);

        float dx = 0.0f, dz = 0.0f;
        #pragma unroll
        for (int j = 0; j < 4; j++) {
            const float4 w  = __ldg(w4 + li + 8 * j);
            const float4 xv = __ldg(x4 + li + 8 * j);
            const float4 zv = __ldg(z4 + li + 8 * j);
            dx += w.x * xv.x + w.y * xv.y + w.z * xv.z + w.w * xv.w;
            dz += w.x * zv.x + w.y * zv.y + w.z * zv.z + w.w * zv.w;
        }
        // reduce across the 8 lanes of this row-group
        #pragma unroll
        for (int off = 4; off; off >>= 1) {
            dx += __shfl_xor_sync(0xffffffffu, dx, off);
            dz += __shfl_xor_sync(0xffffffffu, dz, off);
        }

        if (li == 0) {
            const float lx = expf(dx * INV_T);
            const float lz = expf(dz * INV_T);
            out[(size_t)b * KP1 + k]              = lx;
            out[OUT_LZ_OFF + (size_t)b * KP1 + k] = lz;
            lx_store = lx;
        }
    }

    // combine the 4 group results (lanes 0,8,16,24) then block-reduce
    float s = lx_store;
    s += __shfl_xor_sync(0xffffffffu, s, 8);
    s += __shfl_xor_sync(0xffffffffu, s, 16);
    if (lane == 0) s_part[warp_in_blk] = (double)s;
    __syncthreads();
    if (threadIdx.x == 0) {
        double acc = 0.0;
        #pragma unroll
        for (int i = 0; i < 8; i++) acc += s_part[i];
        atomicAdd(&g_sum, acc);
    }
}

// ---------------------------------------------------------------------------
// Epilogue: scale lx/lz by 1/Z0; blocks 0-1 also do the 16-row EMA scatter.
// ---------------------------------------------------------------------------
__global__ void __launch_bounds__(256) k_finish(
    const float* __restrict__ x, const float* __restrict__ mem,
    const int* __restrict__ y, float* __restrict__ out)
{
    if (blockIdx.x < 2) {
        const int warp = threadIdx.x >> 5;
        const int lane = threadIdx.x & 31;
        const int b    = blockIdx.x * 8 + warp;   // 0..15

        const int row = __ldg(&y[b]);
        const float4 m  = __ldg((const float4*)(mem + (size_t)row * NDIM) + lane);
        const float4 xv = __ldg((const float4*)(x + b * NDIM) + lane);

        float4 w;
        w.x = EMA_M * m.x + (1.0f - EMA_M) * xv.x;
        w.y = EMA_M * m.y + (1.0f - EMA_M) * xv.y;
        w.z = EMA_M * m.z + (1.0f - EMA_M) * xv.z;
        w.w = EMA_M * m.w + (1.0f - EMA_M) * xv.w;

        float nrm = w.x * w.x + w.y * w.y + w.z * w.z + w.w * w.w;
        #pragma unroll
        for (int off = 16; off; off >>= 1)
            nrm += __shfl_xor_sync(0xffffffffu, nrm, off);
        const float inv = rsqrtf(nrm);

        float4 o;
        o.x = w.x * inv; o.y = w.y * inv; o.z = w.z * inv; o.w = w.w * inv;
        ((float4*)(out + OUT_MEM_OFF + (size_t)row * NDIM))[lane] = o;
    }

    const double z0 = g_sum / (double)LOGITS * (double)NDATA;
    const float  inv = (float)(1.0 / z0);

    const size_t i = (size_t)blockIdx.x * 256 + threadIdx.x;
    if (i < N4_SCALE) {
        float4* p = (float4*)out;
        float4 v = p[i];
        v.x *= inv; v.y *= inv; v.z *= inv; v.w *= inv;
        p[i] = v;
    }
}

// ---------------------------------------------------------------------------
extern "C" void kernel_launch(void* const* d_in, const int* in_sizes, int n_in,
                              void* d_out, int out_size)
{
    const float* x   = (const float*)d_in[0];
    const float* z   = (const float*)d_in[1];
    const float* mem = (const float*)d_in[2];
    const int*   y   = (const int*)  d_in[3];
    const int*   idx = (const int*)  d_in[4];
    float*       out = (float*)d_out;

    (void)in_sizes; (void)n_in; (void)out_size;

    k_init<<<1, 1>>>();

    k_fused<<<TOTAL_BLKS, 256>>>(x, z, mem, y, idx, out);

    const unsigned fin_blocks = (unsigned)((N4_SCALE + 255) / 256);  // 2049
    k_finish<<<fin_blocks, 256>>>(x, mem, y, out);
}

// round 3
// speedup vs baseline: 1.7096x; 1.2128x over previous
#include <cuda_runtime.h>
#include <math.h>

#define BSZ    16
#define KNEG   65536
#define KP1    65537u
#define NDIM   128
#define NDATA  1000000
#define INV_T  (1.0f / 0.07f)
#define EMA_M  0.5f

#define LOGITS       (BSZ * 65537)            // 1,048,592 = 4 * 262,148
#define TOT_WARPS    (LOGITS / 4)             // 262,148
#define GBLKS        ((TOT_WARPS + 7) / 8)    // 32,769 blocks, 8 warps each

#define OUT_LZ_OFF   ((size_t)LOGITS)
#define OUT_MEM_OFF  ((size_t)2 * LOGITS)
#define N4_MEM       ((size_t)NDATA * NDIM / 4)     // 32,000,000 float4
#define N4_SCALE     ((size_t)2 * LOGITS / 4)       // 524,296 float4 (exact)
#define CP_STRIDE    ((size_t)GBLKS * 256)          // 8,388,864

#define FIN_BLKS     ((unsigned)((N4_SCALE + 255) / 256))   // 2049

__device__ double       g_sum;    // zero-initialized; k_finish resets it each replay
__device__ unsigned int g_done;   // arrival counter for the reset

// ---------------------------------------------------------------------------
// Every block: (1) gather+dot+exp for 32 logit rows (8 warps x 4 rows,
// 8 lanes/row), (2) a 4-way unrolled streaming-copy slice of memory -> out,
// (3) block-reduce lx into g_sum.
// ---------------------------------------------------------------------------
__global__ void __launch_bounds__(256) k_fused(
    const float* __restrict__ x, const float* __restrict__ z,
    const float* __restrict__ mem, const int* __restrict__ y,
    const int* __restrict__ idx, float* __restrict__ out)
{
    const int warp_in_blk = threadIdx.x >> 5;
    const int lane        = threadIdx.x & 31;
    const int grp         = lane >> 3;     // which of this warp's 4 rows
    const int li          = lane & 7;      // lane within row-group
    const unsigned warp_id = blockIdx.x * 8u + warp_in_blk;

    __shared__ double s_part[8];

    float lx_store = 0.0f;

    // ---------------- gather phase ----------------
    if (warp_id < (unsigned)TOT_WARPS) {
        const unsigned lg = warp_id * 4u + grp;     // logit index < LOGITS < 2^21
        const unsigned b  = lg / KP1;
        const unsigned k  = lg - b * KP1;

        int row;
        if (k == 0) row = __ldg(&y[b]);
        else        row = __ldg(&idx[(size_t)b * KNEG + (k - 1)]);

        const float4* w4 = (const float4*)(mem + (size_t)row * NDIM);
        const float4* x4 = (const float4*)(x + b * NDIM);
        const float4* z4 = (const float4*)(z + b * NDIM);

        float dx = 0.0f, dz = 0.0f;
        #pragma unroll
        for (int j = 0; j < 4; j++) {
            const float4 w  = __ldg(w4 + li + 8 * j);
            const float4 xv = __ldg(x4 + li + 8 * j);
            const float4 zv = __ldg(z4 + li + 8 * j);
            dx += w.x * xv.x + w.y * xv.y + w.z * xv.z + w.w * xv.w;
            dz += w.x * zv.x + w.y * zv.y + w.z * zv.z + w.w * zv.w;
        }
        #pragma unroll
        for (int off = 4; off; off >>= 1) {
            dx += __shfl_xor_sync(0xffffffffu, dx, off);
            dz += __shfl_xor_sync(0xffffffffu, dz, off);
        }

        if (li == 0) {
            const float lx = expf(dx * INV_T);
            const float lz = expf(dz * INV_T);
            out[(size_t)b * KP1 + k]              = lx;
            out[OUT_LZ_OFF + (size_t)b * KP1 + k] = lz;
            lx_store = lx;
        }
    }

    // ---------------- streaming copy slice (4 independent iterations) ------
    {
        const size_t i0 = (size_t)blockIdx.x * 256 + threadIdx.x;  // < CP_STRIDE
        const float4* src = (const float4*)mem;
        float4*       dst = (float4*)(out + OUT_MEM_OFF);

        const float4 v0 = __ldcs(src + i0);                 // i0       < 8.39M ok
        const float4 v1 = __ldcs(src + i0 + CP_STRIDE);     // < 16.78M  ok
        const float4 v2 = __ldcs(src + i0 + 2 * CP_STRIDE); // < 25.17M  ok
        const bool   h3 = (i0 + 3 * CP_STRIDE) < N4_MEM;
        float4 v3;
        if (h3) v3 = __ldcs(src + i0 + 3 * CP_STRIDE);

        __stcs(dst + i0,                 v0);
        __stcs(dst + i0 + CP_STRIDE,     v1);
        __stcs(dst + i0 + 2 * CP_STRIDE, v2);
        if (h3) __stcs(dst + i0 + 3 * CP_STRIDE, v3);
    }

    // ---------------- block reduction into g_sum ---------------------------
    float s = lx_store;                      // nonzero only on lanes 0,8,16,24
    s += __shfl_xor_sync(0xffffffffu, s, 8);
    s += __shfl_xor_sync(0xffffffffu, s, 16);
    if (lane == 0) s_part[warp_in_blk] = (double)s;
    __syncthreads();
    if (threadIdx.x == 0) {
        double acc = 0.0;
        #pragma unroll
        for (int i = 0; i < 8; i++) acc += s_part[i];
        atomicAdd(&g_sum, acc);
    }
}

// ---------------------------------------------------------------------------
// Epilogue: scale lx/lz by 1/Z0; blocks 0-1 do the 16-row EMA scatter; the
// last block to finish resets g_sum/g_done for the next graph replay.
// ---------------------------------------------------------------------------
__global__ void __launch_bounds__(256) k_finish(
    const float* __restrict__ x, const float* __restrict__ mem,
    const int* __restrict__ y, float* __restrict__ out)
{
    __shared__ float s_inv;
    if (threadIdx.x == 0) {
        const double z0 = g_sum / (double)LOGITS * (double)NDATA;
        s_inv = (float)(1.0 / z0);
    }
    __syncthreads();
    const float inv = s_inv;

    if (blockIdx.x < 2) {
        const int warp = threadIdx.x >> 5;
        const int lane = threadIdx.x & 31;
        const int b    = blockIdx.x * 8 + warp;   // 0..15

        const int row = __ldg(&y[b]);
        const float4 m  = __ldg((const float4*)(mem + (size_t)row * NDIM) + lane);
        const float4 xv = __ldg((const float4*)(x + b * NDIM) + lane);

        float4 w;
        w.x = EMA_M * m.x + (1.0f - EMA_M) * xv.x;
        w.y = EMA_M * m.y + (1.0f - EMA_M) * xv.y;
        w.z = EMA_M * m.z + (1.0f - EMA_M) * xv.z;
        w.w = EMA_M * m.w + (1.0f - EMA_M) * xv.w;

        float nrm = w.x * w.x + w.y * w.y + w.z * w.z + w.w * w.w;
        #pragma unroll
        for (int off = 16; off; off >>= 1)
            nrm += __shfl_xor_sync(0xffffffffu, nrm, off);
        const float rinv = rsqrtf(nrm);

        float4 o;
        o.x = w.x * rinv; o.y = w.y * rinv; o.z = w.z * rinv; o.w = w.w * rinv;
        ((float4*)(out + OUT_MEM_OFF + (size_t)row * NDIM))[lane] = o;
    }

    const size_t i = (size_t)blockIdx.x * 256 + threadIdx.x;
    if (i < N4_SCALE) {
        float4* p = (float4*)out;
        float4 v = p[i];
        v.x *= inv; v.y *= inv; v.z *= inv; v.w *= inv;
        p[i] = v;
    }

    // ----- replay-safe reset of the accumulator ----------------------------
    __syncthreads();
    if (threadIdx.x == 0) {
        __threadfence();                      // order g_sum read before arrival
        const unsigned prev = atomicAdd(&g_done, 1u);
        if (prev == FIN_BLKS - 1) {           // last block of this replay
            g_sum  = 0.0;
            g_done = 0u;
            __threadfence();
        }
    }
}

// ---------------------------------------------------------------------------
extern "C" void kernel_launch(void* const* d_in, const int* in_sizes, int n_in,
                              void* d_out, int out_size)
{
    const float* x   = (const float*)d_in[0];
    const float* z   = (const float*)d_in[1];
    const float* mem = (const float*)d_in[2];
    const int*   y   = (const int*)  d_in[3];
    const int*   idx = (const int*)  d_in[4];
    float*       out = (float*)d_out;

    (void)in_sizes; (void)n_in; (void)out_size;

    k_fused<<<GBLKS, 256>>>(x, z, mem, y, idx, out);
    k_finish<<<FIN_BLKS, 256>>>(x, mem, y, out);
}